// round 5
// baseline (speedup 1.0000x reference)
#include <cuda_runtime.h>
#include <cstdint>

// z: [B=2048, TF=120, DL=16]  W: [TF, DL, 672]  bias: [TF, 672]
// out: [B, TF, 16, 43] fp32
#define TF     120
#define DL     16
#define PFEAT  16
#define CHUNK  42
#define RPAD   48           // smem row: [0..21]=gamma/beta cols, [22,23]=0, [24..43]=softmax cols, [44..47]=0
#define OUTC   43
#define OPB    (PFEAT*OUTC) // 688
#define BT     16           // batches per block
#define NTH    512          // 16 b x 16 f x 2 halves
#define SST    689          // staging stride (odd -> conflict-free)
#define ZST    17           // z tile stride (odd -> conflict-free)

__device__ __forceinline__ unsigned long long pack2(float lo, float hi) {
    unsigned long long r;
    asm("mov.b64 %0, {%1, %2};" : "=l"(r) : "f"(lo), "f"(hi));
    return r;
}
__device__ __forceinline__ void unpack2(unsigned long long v, float& lo, float& hi) {
    asm("mov.b64 {%0, %1}, %2;" : "=f"(lo), "=f"(hi) : "l"(v));
}
__device__ __forceinline__ unsigned long long ffma2(unsigned long long a,
                                                    unsigned long long b,
                                                    unsigned long long c) {
    unsigned long long d;
    asm("fma.rn.f32x2 %0, %1, %2, %3;" : "=l"(d) : "l"(a), "l"(b), "l"(c));
    return d;
}

__global__ __launch_bounds__(NTH, 2)
void ddm_spline_kernel(const float* __restrict__ z,
                       const float* __restrict__ W,
                       const float* __restrict__ bias,
                       float* __restrict__ out)
{
    extern __shared__ float smem[];
    float* Ws  = smem;                        // [DL][PFEAT][RPAD] = 12288 floats
    float* bs  = Ws + DL * PFEAT * RPAD;      // [PFEAT][RPAD]    = 768
    float* zs  = bs + PFEAT * RPAD;           // [BT][ZST]        = 272
    float* stg = zs + BT * ZST;               // [BT][SST]        = 11024

    const int tid = threadIdx.x;
    const int t   = blockIdx.y;
    const int b0  = blockIdx.x * BT;
    const int bl  = tid & 15;          // batch in tile
    const int f   = (tid >> 4) & 15;   // feature
    const int hf  = tid >> 8;          // 0: gamma+beta cols, 1: softmax cols

    // ---- W[t] -> padded smem rows (split layout, zero pads) ----
    const float* Wt = W + (size_t)t * (DL * PFEAT * CHUNK);
    #pragma unroll
    for (int it = 0; it < (DL * PFEAT * CHUNK) / NTH; it++) {   // 10752/512 = 21
        int i  = tid + it * NTH;
        int k  = i / (PFEAT * CHUNK);
        int o  = i - k * (PFEAT * CHUNK);
        int ff = o / CHUNK;
        int j  = o - ff * CHUNK;
        int jp = (j < 22) ? j : (j + 2);   // softmax cols shifted to 24..43
        Ws[(k * PFEAT + ff) * RPAD + jp] = Wt[i];
    }
    if (tid < DL * PFEAT) {                 // zero the pad columns
        float* row = &Ws[tid * RPAD];
        row[22] = 0.f; row[23] = 0.f;
        row[44] = 0.f; row[45] = 0.f; row[46] = 0.f; row[47] = 0.f;
    }
    // ---- bias[t] (same padded layout) ----
    {
        const float* bt = bias + (size_t)t * (PFEAT * CHUNK);
        for (int i = tid; i < PFEAT * CHUNK; i += NTH) {
            int ff = i / CHUNK;
            int j  = i - ff * CHUNK;
            int jp = (j < 22) ? j : (j + 2);
            bs[ff * RPAD + jp] = bt[i];
        }
        if (tid < PFEAT) {
            float* row = &bs[tid * RPAD];
            row[22] = 0.f; row[23] = 0.f;
            row[44] = 0.f; row[45] = 0.f; row[46] = 0.f; row[47] = 0.f;
        }
    }
    // ---- z tile ----
    if (tid < BT * DL) {
        int bb = tid >> 4, kk = tid & 15;
        zs[bb * ZST + kk] = z[((size_t)(b0 + bb) * TF + t) * DL + kk];
    }
    __syncthreads();

    // ---- GEMM: 24 columns (12 f32x2 accs) per thread ----
    unsigned long long acc[12];
    {
        const ulonglong2* bp2 =
            reinterpret_cast<const ulonglong2*>(&bs[f * RPAD + hf * 24]);
        #pragma unroll
        for (int q = 0; q < 6; q++) {
            ulonglong2 v = bp2[q];
            acc[2 * q]     = v.x;
            acc[2 * q + 1] = v.y;
        }
    }
    {
        const float* zrow = &zs[bl * ZST];
        const int colbase = hf * 24;
        #pragma unroll
        for (int k = 0; k < DL; k++) {
            float zk = zrow[k];
            unsigned long long zz = pack2(zk, zk);
            const ulonglong2* wr = reinterpret_cast<const ulonglong2*>(
                &Ws[(k * PFEAT + f) * RPAD + colbase]);
            #pragma unroll
            for (int q = 0; q < 6; q++) {
                ulonglong2 w = wr[q];
                acc[2 * q]     = ffma2(zz, w.x, acc[2 * q]);
                acc[2 * q + 1] = ffma2(zz, w.y, acc[2 * q + 1]);
            }
        }
    }

    float hh[24];
    #pragma unroll
    for (int q = 0; q < 12; q++) unpack2(acc[q], hh[2 * q], hh[2 * q + 1]);

    float* srow = &stg[bl * SST + f * OUTC];
    if (hf == 0) {
        // gamma + 21 x softplus  (hh[22..23] are pad, ignored)
        srow[0] = hh[0];
        #pragma unroll
        for (int i = 0; i < 21; i++) {
            float x = hh[1 + i];
            srow[1 + i] = fmaxf(x, 0.f) + __logf(1.f + __expf(-fabsf(x)));
        }
    } else {
        // softmax(hh[0..19] / 0.1) -> cumsum -> delta  (hh[20..23] pad)
        float m = hh[0];
        #pragma unroll
        for (int i = 1; i < 20; i++) m = fmaxf(m, hh[i]);
        float e[20];
        float sum = 0.f;
        #pragma unroll
        for (int i = 0; i < 20; i++) {
            e[i] = __expf((hh[i] - m) * 10.0f);
            sum += e[i];
        }
        float inv = __fdividef(1.0f, sum);
        srow[22] = 0.f;
        float c = 0.f;
        #pragma unroll
        for (int i = 0; i < 20; i++) {
            c += e[i] * inv;
            srow[23 + i] = c;
        }
    }
    __syncthreads();

    // ---- coalesced flush: 16 x 688 contiguous floats per block ----
    for (int i = tid; i < BT * OPB; i += NTH) {   // 11008 -> 21.5 iters
        int blc = i / OPB;
        int r   = i - blc * OPB;
        out[((b0 + blc) * TF + t) * OPB + r] = stg[blc * SST + r];
    }
}

extern "C" void kernel_launch(void* const* d_in, const int* in_sizes, int n_in,
                              void* d_out, int out_size) {
    const float* z    = (const float*)d_in[0];
    const float* W    = (const float*)d_in[1];
    const float* bias = (const float*)d_in[2];
    float* out        = (float*)d_out;

    const int B = in_sizes[0] / (TF * DL);   // 2048
    const size_t shmem =
        (size_t)(DL * PFEAT * RPAD + PFEAT * RPAD + BT * ZST + BT * SST) * sizeof(float);

    cudaFuncSetAttribute(ddm_spline_kernel,
                         cudaFuncAttributeMaxDynamicSharedMemorySize, (int)shmem);

    dim3 grid(B / BT, TF);   // b-tiles fastest -> W[t] stays L2-hot across concurrent blocks
    ddm_spline_kernel<<<grid, NTH, shmem>>>(z, W, bias, out);
}

// round 6
// speedup vs baseline: 1.4452x; 1.4452x over previous
#include <cuda_runtime.h>
#include <cstdint>

// z: [B=2048, TF=120, DL=16]  W: [TF, DL, 672]  bias: [TF, 672]
// out: [B, TF, 16, 43] fp32
#define TF     120
#define DL     16
#define PFEAT  16
#define CHUNK  42
#define RPAD   48           // W smem row: [0..21]=gamma/beta, [22,23]=pad, [24..43]=softmax, [44..47]=pad
#define OUTC   43
#define OPB    (PFEAT*OUTC) // 688
#define BT     16           // batches per tile
#define NTH    512          // 16 bl x 16 f x 2 halves = 16 warps
#define SST    689          // staging stride (odd -> conflict-free STS)
#define ZP     17           // z row stride in float2 units (odd -> conflict-free LDS.64)
#define TILES_PER_BLOCK 8

__device__ __forceinline__ unsigned long long ffma2(unsigned long long a,
                                                    unsigned long long b,
                                                    unsigned long long c) {
    unsigned long long d;
    asm("fma.rn.f32x2 %0, %1, %2, %3;" : "=l"(d) : "l"(a), "l"(b), "l"(c));
    return d;
}

__global__ __launch_bounds__(NTH, 2)
void ddm_spline_kernel(const float* __restrict__ z,
                       const float* __restrict__ W,
                       const float* __restrict__ bias,
                       float* __restrict__ out)
{
    extern __shared__ float smem[];
    float*  Ws  = smem;                            // [DL][PFEAT][RPAD] = 12288 floats
    float*  bs  = Ws + DL * PFEAT * RPAD;          // [PFEAT][RPAD]    = 768
    float2* zs2 = (float2*)(bs + PFEAT * RPAD);    // [BT][ZP] float2  = 544 floats
    float*  stg = (float*)(zs2 + BT * ZP);         // [BT][SST]        = 11024 floats

    const int tid = threadIdx.x;
    const int t   = blockIdx.y;
    const int bb0 = blockIdx.x * (BT * TILES_PER_BLOCK);
    const int bl  = tid & 15;          // batch in tile
    const int f   = (tid >> 4) & 15;   // feature
    const int hf  = tid >> 8;          // 0: gamma+beta cols, 1: softmax cols
    const int wrp = tid >> 5;          // warp id (0..15) for flush
    const int ln  = tid & 31;

    // ---- W[t] -> padded smem (ONCE per block, amortized over 8 tiles) ----
    const float* Wt = W + (size_t)t * (DL * PFEAT * CHUNK);
    #pragma unroll
    for (int it = 0; it < (DL * PFEAT * CHUNK) / NTH; it++) {   // 21 exact
        int i  = tid + it * NTH;
        int k  = i / (PFEAT * CHUNK);
        int o  = i - k * (PFEAT * CHUNK);
        int ff = o / CHUNK;
        int j  = o - ff * CHUNK;
        int jp = (j < 22) ? j : (j + 2);   // softmax cols shifted to 24..43
        Ws[(k * PFEAT + ff) * RPAD + jp] = Wt[i];
    }
    if (tid < DL * PFEAT) {
        float* row = &Ws[tid * RPAD];
        row[22] = 0.f; row[23] = 0.f;
        row[44] = 0.f; row[45] = 0.f; row[46] = 0.f; row[47] = 0.f;
    }
    {   // bias[t] in same padded layout
        const float* bt = bias + (size_t)t * (PFEAT * CHUNK);
        for (int i = tid; i < PFEAT * CHUNK; i += NTH) {
            int ff = i / CHUNK;
            int j  = i - ff * CHUNK;
            int jp = (j < 22) ? j : (j + 2);
            bs[ff * RPAD + jp] = bt[i];
        }
        if (tid < PFEAT) {
            float* row = &bs[tid * RPAD];
            row[22] = 0.f; row[23] = 0.f;
            row[44] = 0.f; row[45] = 0.f; row[46] = 0.f; row[47] = 0.f;
        }
    }

    // steady-state base pointers (all inner offsets are compile-time immediates)
    const unsigned long long* zrow =
        reinterpret_cast<const unsigned long long*>(zs2) + bl * ZP;
    const float* wbase = Ws + f * RPAD + hf * 24;
    const ulonglong2* bini =
        reinterpret_cast<const ulonglong2*>(bs + f * RPAD + hf * 24);
    float* srow = stg + bl * SST + f * OUTC;

    for (int tile = 0; tile < TILES_PER_BLOCK; tile++) {
        const int b0 = bb0 + tile * BT;

        __syncthreads();   // prev flush done reading stg / prev GEMM done reading zs2
        // ---- z tile, stored DUPLICATED (zk,zk) for direct f32x2 multiplier loads ----
        if (tid < BT * DL) {
            int bb = tid >> 4, kk = tid & 15;
            float zv = z[((size_t)(b0 + bb) * TF + t) * DL + kk];
            zs2[bb * ZP + kk] = make_float2(zv, zv);
        }
        __syncthreads();   // z (and on tile 0: W/bias) visible

        // ---- GEMM: 24 columns (12 f32x2 accs), all LDS offsets immediate ----
        unsigned long long acc[12];
        #pragma unroll
        for (int q = 0; q < 6; q++) {
            ulonglong2 v = bini[q];
            acc[2 * q]     = v.x;
            acc[2 * q + 1] = v.y;
        }
        #pragma unroll
        for (int k = 0; k < DL; k++) {
            unsigned long long zz = zrow[k];                     // LDS.64, conflict-free
            const ulonglong2* wr =
                reinterpret_cast<const ulonglong2*>(wbase + k * PFEAT * RPAD);
            #pragma unroll
            for (int q = 0; q < 6; q++) {                        // LDS.128, half-warp broadcast
                ulonglong2 w = wr[q];
                acc[2 * q]     = ffma2(zz, w.x, acc[2 * q]);
                acc[2 * q + 1] = ffma2(zz, w.y, acc[2 * q + 1]);
            }
        }
        float hh[24];
        #pragma unroll
        for (int q = 0; q < 12; q++) {                           // reg-pair alias, no movs
            float2 v = *reinterpret_cast<float2*>(&acc[q]);
            hh[2 * q] = v.x; hh[2 * q + 1] = v.y;
        }

        // ---- transforms -> staging (conflict-free STS) ----
        if (hf == 0) {
            srow[0] = hh[0];                                     // gamma
            #pragma unroll
            for (int i = 0; i < 21; i++) {                       // softplus
                float x = hh[1 + i];
                srow[1 + i] = fmaxf(x, 0.f) + __logf(1.f + __expf(-fabsf(x)));
            }
        } else {
            float m = hh[0];
            #pragma unroll
            for (int i = 1; i < 20; i++) m = fmaxf(m, hh[i]);
            float e[20];
            float sum = 0.f;
            #pragma unroll
            for (int i = 0; i < 20; i++) {
                e[i] = __expf((hh[i] - m) * 10.0f);
                sum += e[i];
            }
            float inv = __fdividef(1.0f, sum);
            srow[22] = 0.f;
            float c = 0.f;
            #pragma unroll
            for (int i = 0; i < 20; i++) {
                c += e[i] * inv;
                srow[23 + i] = c;
            }
        }
        __syncthreads();   // staging visible

        // ---- flush: warp w owns staging row w -> 688 contiguous floats, coalesced ----
        {
            const float* src = stg + wrp * SST;
            float* dst = out + ((size_t)(b0 + wrp) * TF + t) * OPB;
            #pragma unroll
            for (int j = ln; j < OPB; j += 32) {                 // 22 iters, no div
                __stcs(dst + j, src[j]);                         // streaming: keep W in L2
            }
        }
    }
}

extern "C" void kernel_launch(void* const* d_in, const int* in_sizes, int n_in,
                              void* d_out, int out_size) {
    const float* z    = (const float*)d_in[0];
    const float* W    = (const float*)d_in[1];
    const float* bias = (const float*)d_in[2];
    float* out        = (float*)d_out;

    const int B = in_sizes[0] / (TF * DL);            // 2048
    const int splits = B / (BT * TILES_PER_BLOCK);    // 16

    const size_t shmem =
        (size_t)(DL * PFEAT * RPAD + PFEAT * RPAD + BT * ZP * 2 + BT * SST) * sizeof(float);

    cudaFuncSetAttribute(ddm_spline_kernel,
                         cudaFuncAttributeMaxDynamicSharedMemorySize, (int)shmem);

    dim3 grid(splits, TF);
    ddm_spline_kernel<<<grid, NTH, shmem>>>(z, W, bias, out);
}

// round 7
// speedup vs baseline: 1.7889x; 1.2378x over previous
#include <cuda_runtime.h>
#include <cstdint>

// z: [B=2048, TF=120, DL=16]  W: [TF, DL, 672]  bias: [TF, 672]
// out: [B, TF, 16, 43] fp32
#define TF     120
#define DL     16
#define PFEAT  16
#define CHUNK  42
#define RPAD   48           // W smem row: [0..21]=gamma/beta, [22,23]=pad, [24..43]=softmax, [44..47]=pad
#define OUTC   43
#define OPB    (PFEAT*OUTC) // 688
#define BT     16           // batches per tile (each thread: 2 of them)
#define NTH    256          // 8 bl x 16 f x 2 hf
#define SST    692          // staging stride: 692/4=173 float4 (16B-aligned rows), conflict-free STS
#define ZP     17           // z row stride in float2 units (odd -> conflict-free LDS.64)
#define TILES_PER_BLOCK 8

__device__ __forceinline__ unsigned long long ffma2(unsigned long long a,
                                                    unsigned long long b,
                                                    unsigned long long c) {
    unsigned long long d;
    asm("fma.rn.f32x2 %0, %1, %2, %3;" : "=l"(d) : "l"(a), "l"(b), "l"(c));
    return d;
}

__global__ __launch_bounds__(NTH, 2)
void ddm_spline_kernel(const float* __restrict__ z,
                       const float* __restrict__ W,
                       const float* __restrict__ bias,
                       float* __restrict__ out)
{
    extern __shared__ float smem[];
    float*  Ws  = smem;                            // [DL][PFEAT][RPAD] = 12288 floats
    float*  bs  = Ws + DL * PFEAT * RPAD;          // [PFEAT][RPAD]    = 768
    float2* zs2 = (float2*)(bs + PFEAT * RPAD);    // [BT][ZP] float2  = 544 floats
    float*  stg = (float*)(zs2 + BT * ZP);         // [BT][SST]        = 11072 floats

    const int tid = threadIdx.x;
    const int t   = blockIdx.y;
    const int bb0 = blockIdx.x * (BT * TILES_PER_BLOCK);
    const int bl  = tid & 7;           // batch slot (thread also handles bl+8)
    const int f   = (tid >> 3) & 15;   // feature
    const int hf  = tid >> 7;          // 0: gamma+beta cols, 1: softmax cols
    const int wrp = tid >> 5;          // warp id (0..7) for flush
    const int ln  = tid & 31;

    // ---- W[t] -> padded smem (once per block, amortized over 8 tiles) ----
    const float* Wt = W + (size_t)t * (DL * PFEAT * CHUNK);
    for (int it = 0; it < (DL * PFEAT * CHUNK) / NTH; it++) {   // 42 exact
        int i  = tid + it * NTH;
        int k  = i / (PFEAT * CHUNK);
        int o  = i - k * (PFEAT * CHUNK);
        int ff = o / CHUNK;
        int j  = o - ff * CHUNK;
        int jp = (j < 22) ? j : (j + 2);   // softmax cols shifted to 24..43
        Ws[(k * PFEAT + ff) * RPAD + jp] = Wt[i];
    }
    if (tid < DL * PFEAT) {
        float* row = &Ws[tid * RPAD];
        row[22] = 0.f; row[23] = 0.f;
        row[44] = 0.f; row[45] = 0.f; row[46] = 0.f; row[47] = 0.f;
    }
    {   // bias[t], same padded layout
        const float* bt = bias + (size_t)t * (PFEAT * CHUNK);
        for (int i = tid; i < PFEAT * CHUNK; i += NTH) {
            int ff = i / CHUNK;
            int j  = i - ff * CHUNK;
            int jp = (j < 22) ? j : (j + 2);
            bs[ff * RPAD + jp] = bt[i];
        }
        if (tid < PFEAT) {
            float* row = &bs[tid * RPAD];
            row[22] = 0.f; row[23] = 0.f;
            row[44] = 0.f; row[45] = 0.f; row[46] = 0.f; row[47] = 0.f;
        }
    }

    // steady-state base pointers (inner offsets become immediates)
    const unsigned long long* zrowA =
        reinterpret_cast<const unsigned long long*>(zs2) + bl * ZP;
    const unsigned long long* zrowB = zrowA + 8 * ZP;
    const float* wbase = Ws + f * RPAD + hf * 24;
    const ulonglong2* bini =
        reinterpret_cast<const ulonglong2*>(bs + f * RPAD + hf * 24);
    float* srowA = stg + bl * SST + f * OUTC;
    float* srowB = srowA + 8 * SST;

    for (int tile = 0; tile < TILES_PER_BLOCK; tile++) {
        const int b0 = bb0 + tile * BT;

        __syncthreads();   // prior flush done with stg, prior GEMM done with zs2
        // z tile, duplicated (zk,zk) for direct f32x2 multiplier loads
        {
            int bb = tid >> 4, kk = tid & 15;   // BT*DL == NTH
            float zv = z[((size_t)(b0 + bb) * TF + t) * DL + kk];
            zs2[bb * ZP + kk] = make_float2(zv, zv);
        }
        __syncthreads();

        // ---- GEMM: 24 cols x 2 batches; each W load feeds 4 ffma2 ----
        unsigned long long accA[12], accB[12];
        #pragma unroll
        for (int q = 0; q < 6; q++) {
            ulonglong2 v = bini[q];
            accA[2 * q] = v.x;  accA[2 * q + 1] = v.y;
            accB[2 * q] = v.x;  accB[2 * q + 1] = v.y;
        }
        #pragma unroll
        for (int k = 0; k < DL; k++) {
            unsigned long long za = zrowA[k];
            unsigned long long zb = zrowB[k];
            const ulonglong2* wr =
                reinterpret_cast<const ulonglong2*>(wbase + k * PFEAT * RPAD);
            #pragma unroll
            for (int q = 0; q < 6; q++) {
                ulonglong2 w = wr[q];
                accA[2 * q]     = ffma2(za, w.x, accA[2 * q]);
                accA[2 * q + 1] = ffma2(za, w.y, accA[2 * q + 1]);
                accB[2 * q]     = ffma2(zb, w.x, accB[2 * q]);
                accB[2 * q + 1] = ffma2(zb, w.y, accB[2 * q + 1]);
            }
        }

        // ---- transforms (both batches) -> staging ----
        #pragma unroll
        for (int which = 0; which < 2; which++) {
            const unsigned long long* acc = which ? accB : accA;
            float* srow = which ? srowB : srowA;
            float hh[24];
            #pragma unroll
            for (int q = 0; q < 12; q++) {
                float2 v = *reinterpret_cast<const float2*>(&acc[q]);
                hh[2 * q] = v.x; hh[2 * q + 1] = v.y;
            }
            if (hf == 0) {
                srow[0] = hh[0];                                 // gamma
                #pragma unroll
                for (int i = 0; i < 21; i++) {                   // softplus
                    float x = hh[1 + i];
                    srow[1 + i] = fmaxf(x, 0.f) + __logf(1.f + __expf(-fabsf(x)));
                }
            } else {
                float m = hh[0];
                #pragma unroll
                for (int i = 1; i < 20; i++) m = fmaxf(m, hh[i]);
                float e[20];
                float sum = 0.f;
                #pragma unroll
                for (int i = 0; i < 20; i++) {
                    e[i] = __expf((hh[i] - m) * 10.0f);
                    sum += e[i];
                }
                float inv = __fdividef(1.0f, sum);
                srow[22] = 0.f;
                float c = 0.f;
                #pragma unroll
                for (int i = 0; i < 20; i++) {
                    c += e[i] * inv;
                    srow[23 + i] = c;
                }
            }
        }
        __syncthreads();   // staging visible

        // ---- flush: warp w owns rows w and w+8; float4 LDS + streaming STG.128 ----
        #pragma unroll
        for (int rr = 0; rr < 2; rr++) {
            const int r = wrp + rr * 8;
            const float4* src4 = reinterpret_cast<const float4*>(stg + r * SST);
            float4* dst4 = reinterpret_cast<float4*>(
                out + ((size_t)(b0 + r) * TF + t) * OPB);
            #pragma unroll
            for (int j = ln; j < OPB / 4; j += 32) {   // 172 float4 -> 5-6 iters
                __stcs(dst4 + j, src4[j]);
            }
        }
    }
}

extern "C" void kernel_launch(void* const* d_in, const int* in_sizes, int n_in,
                              void* d_out, int out_size) {
    const float* z    = (const float*)d_in[0];
    const float* W    = (const float*)d_in[1];
    const float* bias = (const float*)d_in[2];
    float* out        = (float*)d_out;

    const int B = in_sizes[0] / (TF * DL);            // 2048
    const int splits = B / (BT * TILES_PER_BLOCK);    // 16

    const size_t shmem =
        (size_t)(DL * PFEAT * RPAD + PFEAT * RPAD + BT * ZP * 2 + BT * SST) * sizeof(float);

    cudaFuncSetAttribute(ddm_spline_kernel,
                         cudaFuncAttributeMaxDynamicSharedMemorySize, (int)shmem);

    dim3 grid(splits, TF);
    ddm_spline_kernel<<<grid, NTH, shmem>>>(z, W, bias, out);
}

// round 8
// speedup vs baseline: 1.9170x; 1.0716x over previous
#include <cuda_runtime.h>
#include <cstdint>

// z: [B=2048, TF=120, DL=16]  W: [TF, DL, 672]  bias: [TF, 672]
// out: [B, TF, 16, 43] fp32
#define TF     120
#define DL     16
#define PFEAT  16
#define CHUNK  42
#define RPAD   44           // W smem row: cols 0..41 real, 42..43 junk (never used)
#define OUTC   43
#define OPB    (PFEAT*OUTC) // 688
#define BT     16           // batches per tile (each thread: 2 of them)
#define NTH    256          // 8 bl x 16 f x 2 hf
#define SST    692          // staging stride: 173 float4, 16B-aligned rows, conflict-free
#define ZP     17           // z row stride in float2 units (odd -> conflict-free LDS.64)
#define TILES_PER_BLOCK 8

__device__ __forceinline__ unsigned long long ffma2(unsigned long long a,
                                                    unsigned long long b,
                                                    unsigned long long c) {
    unsigned long long d;
    asm("fma.rn.f32x2 %0, %1, %2, %3;" : "=l"(d) : "l"(a), "l"(b), "l"(c));
    return d;
}

__global__ __launch_bounds__(NTH, 2)
void ddm_spline_kernel(const float* __restrict__ z,
                       const float* __restrict__ W,
                       const float* __restrict__ bias,
                       float* __restrict__ out)
{
    extern __shared__ float smem[];
    float*  Ws  = smem;                            // [DL][PFEAT][RPAD] = 11264 floats
    float*  bs  = Ws + DL * PFEAT * RPAD;          // [PFEAT][RPAD]    = 704
    float2* zs2 = (float2*)(bs + PFEAT * RPAD);    // 2 x [BT][ZP] f2  = 1088 floats
    float*  stg = (float*)(zs2 + 2 * BT * ZP);     // [BT][SST]        = 11072 floats

    const int tid = threadIdx.x;
    const int t   = blockIdx.y;
    const int bb0 = blockIdx.x * (BT * TILES_PER_BLOCK);
    const int bl  = tid & 7;           // batch slot (thread also handles bl+8)
    const int f   = (tid >> 3) & 15;   // feature
    const int hf  = tid >> 7;          // 0: cols 0..23 (gamma/beta), 1: cols 20..43 (softmax)
    const int wrp = tid >> 5;          // warp id (0..7) for flush
    const int ln  = tid & 31;

    // ---- W[t] -> smem, straight copy (once per block) ----
    const float* Wt = W + (size_t)t * (DL * PFEAT * CHUNK);
    for (int it = 0; it < (DL * PFEAT * CHUNK) / NTH; it++) {   // 42 exact
        int i  = tid + it * NTH;
        int k  = i / (PFEAT * CHUNK);
        int r  = i - k * (PFEAT * CHUNK);
        int ff = r / CHUNK;
        int j  = r - ff * CHUNK;
        Ws[(k * PFEAT + ff) * RPAD + j] = Wt[i];
    }
    {   // bias[t]
        const float* bt = bias + (size_t)t * (PFEAT * CHUNK);
        for (int i = tid; i < PFEAT * CHUNK; i += NTH) {
            int ff = i / CHUNK;
            int j  = i - ff * CHUNK;
            bs[ff * RPAD + j] = bt[i];
        }
    }
    // ---- z for tile 0 into buffer 0 (overlaps W fill latency) ----
    {
        int bb = tid >> 4, kk = tid & 15;   // BT*DL == NTH
        float zv = __ldcs(&z[((size_t)(bb0 + bb) * TF + t) * DL + kk]);
        zs2[bb * ZP + kk] = make_float2(zv, zv);
    }
    __syncthreads();

    // steady-state base pointers
    const float* wbase = Ws + f * RPAD + hf * 20;          // 16B-aligned (80B)
    const ulonglong2* bini =
        reinterpret_cast<const ulonglong2*>(bs + f * RPAD + hf * 20);
    float* srowA = stg + bl * SST + f * OUTC;
    float* srowB = srowA + 8 * SST;

    for (int tile = 0; tile < TILES_PER_BLOCK; tile++) {
        const int b0 = bb0 + tile * BT;
        const unsigned long long* zbuf =
            reinterpret_cast<const unsigned long long*>(zs2) + (tile & 1) * (BT * ZP);
        const unsigned long long* zrowA = zbuf + bl * ZP;
        const unsigned long long* zrowB = zrowA + 8 * ZP;

        // ---- GEMM: 24 cols x 2 batches; each W load feeds 4 ffma2 ----
        unsigned long long accA[12], accB[12];
        #pragma unroll
        for (int q = 0; q < 6; q++) {
            ulonglong2 v = bini[q];
            accA[2 * q] = v.x;  accA[2 * q + 1] = v.y;
            accB[2 * q] = v.x;  accB[2 * q + 1] = v.y;
        }
        #pragma unroll
        for (int k = 0; k < DL; k++) {
            unsigned long long za = zrowA[k];
            unsigned long long zb = zrowB[k];
            const ulonglong2* wr =
                reinterpret_cast<const ulonglong2*>(wbase + k * PFEAT * RPAD);
            #pragma unroll
            for (int q = 0; q < 6; q++) {
                ulonglong2 w = wr[q];
                accA[2 * q]     = ffma2(za, w.x, accA[2 * q]);
                accA[2 * q + 1] = ffma2(za, w.y, accA[2 * q + 1]);
                accB[2 * q]     = ffma2(zb, w.x, accB[2 * q]);
                accB[2 * q + 1] = ffma2(zb, w.y, accB[2 * q + 1]);
            }
        }

        // ---- transforms (both batches) -> staging ----
        #pragma unroll
        for (int which = 0; which < 2; which++) {
            const unsigned long long* acc = which ? accB : accA;
            float* srow = which ? srowB : srowA;
            float hh[24];
            #pragma unroll
            for (int q = 0; q < 12; q++) {
                float2 v = *reinterpret_cast<const float2*>(&acc[q]);
                hh[2 * q] = v.x; hh[2 * q + 1] = v.y;
            }
            if (hf == 0) {
                // cols 0..23: gamma = hh[0], beta = softplus(hh[1..21]); hh[22,23] junk
                srow[0] = hh[0];
                #pragma unroll
                for (int i = 0; i < 21; i++) {
                    float x = hh[1 + i];
                    srow[1 + i] = fmaxf(x, 0.f) + __logf(1.f + __expf(-fabsf(x)));
                }
            } else {
                // cols 20..43: logits = hh[2..21]; hh[0,1,22,23] junk
                float m = hh[2];
                #pragma unroll
                for (int i = 1; i < 20; i++) m = fmaxf(m, hh[2 + i]);
                float e[20];
                float sum = 0.f;
                #pragma unroll
                for (int i = 0; i < 20; i++) {
                    e[i] = __expf((hh[2 + i] - m) * 10.0f);
                    sum += e[i];
                }
                float inv = __fdividef(1.0f, sum);
                srow[22] = 0.f;
                float c = 0.f;
                #pragma unroll
                for (int i = 0; i < 20; i++) {
                    c += e[i] * inv;
                    srow[23 + i] = c;
                }
            }
        }
        __syncthreads();   // stg visible; all GEMMs done -> both z buffers safe

        // ---- prefetch z for next tile into the other buffer (hidden under flush) ----
        if (tile + 1 < TILES_PER_BLOCK) {
            int bb = tid >> 4, kk = tid & 15;
            float zv = __ldcs(&z[((size_t)(b0 + BT + bb) * TF + t) * DL + kk]);
            float2* znext = zs2 + ((tile + 1) & 1) * (BT * ZP);
            znext[bb * ZP + kk] = make_float2(zv, zv);
        }

        // ---- flush: warp w owns rows w and w+8; float4 LDS + streaming STG.128 ----
        #pragma unroll
        for (int rr = 0; rr < 2; rr++) {
            const int r = wrp + rr * 8;
            const float4* src4 = reinterpret_cast<const float4*>(stg + r * SST);
            float4* dst4 = reinterpret_cast<float4*>(
                out + ((size_t)(b0 + r) * TF + t) * OPB);
            for (int j = ln; j < OPB / 4; j += 32) {   // 172 float4
                __stcs(dst4 + j, src4[j]);
            }
        }
        __syncthreads();   // flush done (stg free), z[next] visible
    }
}

extern "C" void kernel_launch(void* const* d_in, const int* in_sizes, int n_in,
                              void* d_out, int out_size) {
    const float* z    = (const float*)d_in[0];
    const float* W    = (const float*)d_in[1];
    const float* bias = (const float*)d_in[2];
    float* out        = (float*)d_out;

    const int B = in_sizes[0] / (TF * DL);            // 2048
    const int splits = B / (BT * TILES_PER_BLOCK);    // 16

    const size_t shmem =
        (size_t)(DL * PFEAT * RPAD + PFEAT * RPAD + 2 * BT * ZP * 2 + BT * SST) * sizeof(float);

    cudaFuncSetAttribute(ddm_spline_kernel,
                         cudaFuncAttributeMaxDynamicSharedMemorySize, (int)shmem);

    dim3 grid(splits, TF);
    ddm_spline_kernel<<<grid, NTH, shmem>>>(z, W, bias, out);
}

// round 9
// speedup vs baseline: 2.2461x; 1.1717x over previous
#include <cuda_runtime.h>
#include <cstdint>

// z: [B=2048, TF=120, DL=16]  W: [TF, DL, 672]  bias: [TF, 672]
// out: [B, TF, 16, 43] fp32
#define TF     120
#define DL     16
#define PFEAT  16
#define CHUNK  42
#define RPAD   44           // W smem row: cols 0..41 real, 42..43 junk
#define OUTC   43
#define OPB    (PFEAT*OUTC) // 688 floats = 2752 B per (b,t), contiguous
#define BT     16           // batches per tile (each thread: 2 of them)
#define NTH    256          // 8 bl x 16 f x 2 hf
#define SST    692          // staging stride: 16B-aligned rows, conflict-free
#define ZP     17           // z row stride in float2 units (odd -> conflict-free LDS.64)
#define TILES_PER_BLOCK 8

__device__ __forceinline__ unsigned long long ffma2(unsigned long long a,
                                                    unsigned long long b,
                                                    unsigned long long c) {
    unsigned long long d;
    asm("fma.rn.f32x2 %0, %1, %2, %3;" : "=l"(d) : "l"(a), "l"(b), "l"(c));
    return d;
}
__device__ __forceinline__ uint32_t smem_u32(const void* p) {
    uint32_t a;
    asm("{ .reg .u64 t; cvta.to.shared.u64 t, %1; cvt.u32.u64 %0, t; }"
        : "=r"(a) : "l"(p));
    return a;
}
__device__ __forceinline__ void bulk_s2g(void* gdst, uint32_t ssrc, uint32_t bytes) {
    asm volatile("cp.async.bulk.global.shared::cta.bulk_group [%0], [%1], %2;"
                 :: "l"(gdst), "r"(ssrc), "r"(bytes) : "memory");
}

__global__ __launch_bounds__(NTH, 2)
void ddm_spline_kernel(const float* __restrict__ z,
                       const float* __restrict__ W,
                       const float* __restrict__ bias,
                       float* __restrict__ out)
{
    extern __shared__ float smem[];
    float*  Ws  = smem;                            // [DL][PFEAT][RPAD] = 11264 floats
    float*  bs  = Ws + DL * PFEAT * RPAD;          // [PFEAT][RPAD]    = 704
    float2* zs2 = (float2*)(bs + PFEAT * RPAD);    // 2 x [BT][ZP] f2  = 1088 floats
    float*  stg = (float*)(zs2 + 2 * BT * ZP);     // [BT][SST]        = 11072 floats

    const int tid = threadIdx.x;
    const int t   = blockIdx.y;
    const int bb0 = blockIdx.x * (BT * TILES_PER_BLOCK);
    const int bl  = tid & 7;           // batch slot (thread also handles bl+8)
    const int f   = (tid >> 3) & 15;   // feature
    const int hf  = tid >> 7;          // 0: cols 0..23 (gamma/beta), 1: cols 20..43 (softmax)
    const int wrp = tid >> 5;          // warp id (0..7): flush issuer for rows wrp, wrp+8
    const int ln  = tid & 31;

    // ---- W[t] -> smem, straight copy (once per block) ----
    const float* Wt = W + (size_t)t * (DL * PFEAT * CHUNK);
    for (int it = 0; it < (DL * PFEAT * CHUNK) / NTH; it++) {   // 42 exact
        int i  = tid + it * NTH;
        int k  = i / (PFEAT * CHUNK);
        int r  = i - k * (PFEAT * CHUNK);
        int ff = r / CHUNK;
        int j  = r - ff * CHUNK;
        Ws[(k * PFEAT + ff) * RPAD + j] = Wt[i];
    }
    {   // bias[t]
        const float* bt = bias + (size_t)t * (PFEAT * CHUNK);
        for (int i = tid; i < PFEAT * CHUNK; i += NTH) {
            int ff = i / CHUNK;
            int j  = i - ff * CHUNK;
            bs[ff * RPAD + j] = bt[i];
        }
    }
    // ---- z for tile 0 into buffer 0 ----
    const int zbb = tid >> 4, zkk = tid & 15;       // BT*DL == NTH
    zs2[zbb * ZP + zkk] = make_float2(
        __ldcs(&z[((size_t)(bb0 + zbb) * TF + t) * DL + zkk]),
        __ldcs(&z[((size_t)(bb0 + zbb) * TF + t) * DL + zkk]));
    __syncthreads();

    // steady-state base pointers
    const float* wbase = Ws + f * RPAD + hf * 20;          // 16B-aligned (80B)
    const ulonglong2* bini =
        reinterpret_cast<const ulonglong2*>(bs + f * RPAD + hf * 20);
    float* srowA = stg + bl * SST + f * OUTC;
    float* srowB = srowA + 8 * SST;
    const uint32_t stg_sA = smem_u32(stg + wrp * SST);
    const uint32_t stg_sB = smem_u32(stg + (wrp + 8) * SST);

    for (int tile = 0; tile < TILES_PER_BLOCK; tile++) {
        const int b0 = bb0 + tile * BT;

        // prefetch z for tile+1 into a register (consumed after mid barrier)
        float zv_next = 0.f;
        if (tile + 1 < TILES_PER_BLOCK)
            zv_next = __ldcs(&z[((size_t)(b0 + BT + zbb) * TF + t) * DL + zkk]);

        const unsigned long long* zbuf =
            reinterpret_cast<const unsigned long long*>(zs2) + (tile & 1) * (BT * ZP);
        const unsigned long long* zrowA = zbuf + bl * ZP;
        const unsigned long long* zrowB = zrowA + 8 * ZP;

        // ---- GEMM: 24 cols x 2 batches; each W load feeds 4 ffma2 ----
        unsigned long long accA[12], accB[12];
        #pragma unroll
        for (int q = 0; q < 6; q++) {
            ulonglong2 v = bini[q];
            accA[2 * q] = v.x;  accA[2 * q + 1] = v.y;
            accB[2 * q] = v.x;  accB[2 * q + 1] = v.y;
        }
        #pragma unroll
        for (int k = 0; k < DL; k++) {
            unsigned long long za = zrowA[k];
            unsigned long long zb = zrowB[k];
            const ulonglong2* wr =
                reinterpret_cast<const ulonglong2*>(wbase + k * PFEAT * RPAD);
            #pragma unroll
            for (int q = 0; q < 6; q++) {
                ulonglong2 w = wr[q];
                accA[2 * q]     = ffma2(za, w.x, accA[2 * q]);
                accA[2 * q + 1] = ffma2(za, w.y, accA[2 * q + 1]);
                accB[2 * q]     = ffma2(zb, w.x, accB[2 * q]);
                accB[2 * q + 1] = ffma2(zb, w.y, accB[2 * q + 1]);
            }
        }

        // ---- previous tile's bulk stores must be done READING stg ----
        if (ln == 0)
            asm volatile("cp.async.bulk.wait_group.read 0;" ::: "memory");
        __syncthreads();

        // ---- transforms (both batches) -> staging ----
        #pragma unroll
        for (int which = 0; which < 2; which++) {
            const unsigned long long* acc = which ? accB : accA;
            float* srow = which ? srowB : srowA;
            float hh[24];
            #pragma unroll
            for (int q = 0; q < 12; q++) {
                float2 v = *reinterpret_cast<const float2*>(&acc[q]);
                hh[2 * q] = v.x; hh[2 * q + 1] = v.y;
            }
            if (hf == 0) {
                srow[0] = hh[0];                                 // gamma
                #pragma unroll
                for (int i = 0; i < 21; i++) {                   // softplus
                    float x = hh[1 + i];
                    srow[1 + i] = fmaxf(x, 0.f) + __logf(1.f + __expf(-fabsf(x)));
                }
            } else {
                float m = hh[2];                                 // logits = hh[2..21]
                #pragma unroll
                for (int i = 1; i < 20; i++) m = fmaxf(m, hh[2 + i]);
                float e[20];
                float sum = 0.f;
                #pragma unroll
                for (int i = 0; i < 20; i++) {
                    e[i] = __expf((hh[2 + i] - m) * 10.0f);
                    sum += e[i];
                }
                float inv = __fdividef(1.0f, sum);
                srow[22] = 0.f;
                float c = 0.f;
                #pragma unroll
                for (int i = 0; i < 20; i++) {
                    c += e[i] * inv;
                    srow[23 + i] = c;
                }
            }
        }

        // z for next tile -> other buffer (its last reader finished 1 tile ago)
        if (tile + 1 < TILES_PER_BLOCK) {
            float2* znext = zs2 + ((tile + 1) & 1) * (BT * ZP);
            znext[zbb * ZP + zkk] = make_float2(zv_next, zv_next);
        }

        asm volatile("fence.proxy.async.shared::cta;" ::: "memory");
        __syncthreads();   // stg complete + fenced for async proxy

        // ---- flush via bulk copy engine: 2 rows per warp, issued by lane 0 ----
        if (ln == 0) {
            bulk_s2g(out + ((size_t)(b0 + wrp) * TF + t) * OPB,      stg_sA, OPB * 4);
            bulk_s2g(out + ((size_t)(b0 + wrp + 8) * TF + t) * OPB,  stg_sB, OPB * 4);
            asm volatile("cp.async.bulk.commit_group;" ::: "memory");
        }
    }
    // drain before exit
    if (ln == 0)
        asm volatile("cp.async.bulk.wait_group 0;" ::: "memory");
}

extern "C" void kernel_launch(void* const* d_in, const int* in_sizes, int n_in,
                              void* d_out, int out_size) {
    const float* z    = (const float*)d_in[0];
    const float* W    = (const float*)d_in[1];
    const float* bias = (const float*)d_in[2];
    float* out        = (float*)d_out;

    const int B = in_sizes[0] / (TF * DL);            // 2048
    const int splits = B / (BT * TILES_PER_BLOCK);    // 16

    const size_t shmem =
        (size_t)(DL * PFEAT * RPAD + PFEAT * RPAD + 2 * BT * ZP * 2 + BT * SST) * sizeof(float);

    cudaFuncSetAttribute(ddm_spline_kernel,
                         cudaFuncAttributeMaxDynamicSharedMemorySize, (int)shmem);

    dim3 grid(splits, TF);
    ddm_spline_kernel<<<grid, NTH, shmem>>>(z, W, bias, out);
}